// round 10
// baseline (speedup 1.0000x reference)
#include <cuda_runtime.h>
#include <cstdint>
#include <math.h>

#define H 128
#define MAXB 8192
#define RPB 8   // rows per MLP block

__device__ int   g_starts[MAXB + 1];
__device__ float g_sent[(size_t)MAXB * H];

#define CP_ASYNC_CG(dst_u32, src_ptr) \
    asm volatile("cp.async.cg.shared.global [%0], [%1], 16;" :: "r"(dst_u32), "l"(src_ptr))
#define CP_COMMIT() asm volatile("cp.async.commit_group;")
#define CP_WAIT1()  asm volatile("cp.async.wait_group 1;" ::: "memory")

// ---------------------------------------------------------------------------
// Kernel 0: prepass. 8 tokens/thread via two independent int4 loads (3 loads
// in flight per thread). Builds g_starts from sorted segment_ids and zeroes
// the output scalar.
// ---------------------------------------------------------------------------
__global__ __launch_bounds__(256) void prepass_kernel(
    const int* __restrict__ seg_ids, float* __restrict__ out, int T, int B)
{
    const int gid = blockIdx.x * blockDim.x + threadIdx.x;
    if (gid == 0) *out = 0.0f;

    const int i0 = gid * 8;
    if (i0 >= T) return;

    int v[8];
    if (i0 + 7 < T) {
        const int4 q0 = __ldg(&((const int4*)seg_ids)[gid * 2 + 0]);
        const int4 q1 = __ldg(&((const int4*)seg_ids)[gid * 2 + 1]);
        v[0] = q0.x; v[1] = q0.y; v[2] = q0.z; v[3] = q0.w;
        v[4] = q1.x; v[5] = q1.y; v[6] = q1.z; v[7] = q1.w;
    } else {
        for (int j = 0; j < 8; j++)
            v[j] = (i0 + j < T) ? __ldg(&seg_ids[i0 + j]) : v[j > 0 ? j - 1 : 0];
    }

    int prev = (i0 == 0) ? -1 : __ldg(&seg_ids[i0 - 1]);
#pragma unroll
    for (int j = 0; j < 8; j++) {
        const int i = i0 + j;
        if (i >= T) break;
        const int cur = v[j];
        for (int s = prev + 1; s <= cur; s++) g_starts[s] = i;
        if (i == T - 1)
            for (int s = cur + 1; s <= B; s++) g_starts[s] = T;
        prev = cur;
    }
}

// ---------------------------------------------------------------------------
// Kernel 1: gather + segment mean via cp.async double-buffering.
// One CTA per segment. Warp w owns rows c*16 + 4w + {0..3} of its segment.
// In-flight bytes live in SMEM (not registers) -> low regs + high occupancy.
// Warp-private pipeline: NO barriers in the mainloop.
// ---------------------------------------------------------------------------
__global__ __launch_bounds__(128) void seg_mean_kernel(
    const int*   __restrict__ token_ids,
    const float* __restrict__ embed)
{
    const int seg = blockIdx.x;
    const int tid = threadIdx.x;
    const int w   = tid >> 5;
    const int l   = tid & 31;

    const int start = __ldg(&g_starts[seg]);
    const int end   = __ldg(&g_starts[seg + 1]);
    const int n     = end - start;
    const int chunks = (n + 15) >> 4;

    __shared__ __align__(16) float4 s_buf[4][2][4][32];  // [warp][slot][row][lane] 16KB
    __shared__ float s_part[4][H];

    const unsigned int sbase =
        (unsigned int)__cvta_generic_to_shared(&s_buf[w][0][0][l]);
    const char* E = (const char*)embed;

    float4 a0 = make_float4(0.f, 0.f, 0.f, 0.f), a1 = a0;

#define FILL(c)                                                            \
    do {                                                                   \
        const int _c = (c);                                                \
        if (_c < chunks) {                                                 \
            const int _base = start + _c * 16 + w * 4;                     \
            _Pragma("unroll")                                              \
            for (int _j = 0; _j < 4; _j++) {                               \
                const int _idx = _base + _j;                               \
                if (_idx < end) {                                          \
                    const int _tok = __ldg(&token_ids[_idx]);              \
                    CP_ASYNC_CG(sbase + (unsigned int)((_c & 1) * 2048 + _j * 512), \
                                E + (size_t)_tok * 512 + l * 16);          \
                }                                                          \
            }                                                              \
        }                                                                  \
        CP_COMMIT();                                                       \
    } while (0)

    FILL(0);
    FILL(1);

    for (int c = 0; c < chunks; c++) {
        CP_WAIT1();                          // chunk c complete (c+1 may pend)
        const int base = c * 16 + w * 4;
        const int m    = n - base;
        const int slot = c & 1;
        if (m >= 1) { const float4 v = s_buf[w][slot][0][l];
                      a0.x += v.x; a0.y += v.y; a0.z += v.z; a0.w += v.w; }
        if (m >= 2) { const float4 v = s_buf[w][slot][1][l];
                      a1.x += v.x; a1.y += v.y; a1.z += v.z; a1.w += v.w; }
        if (m >= 3) { const float4 v = s_buf[w][slot][2][l];
                      a0.x += v.x; a0.y += v.y; a0.z += v.z; a0.w += v.w; }
        if (m >= 4) { const float4 v = s_buf[w][slot][3][l];
                      a1.x += v.x; a1.y += v.y; a1.z += v.z; a1.w += v.w; }
        FILL(c + 2);
    }
#undef FILL

    float4 asum;
    asum.x = a0.x + a1.x;  asum.y = a0.y + a1.y;
    asum.z = a0.z + a1.z;  asum.w = a0.w + a1.w;
    *(float4*)&s_part[w][4 * l] = asum;
    __syncthreads();

    const float inv = 1.0f / (float)max(n, 1);
    g_sent[(size_t)seg * H + tid] =
        ((s_part[0][tid] + s_part[1][tid]) +
         (s_part[2][tid] + s_part[3][tid])) * inv;
}

// ---------------------------------------------------------------------------
// Kernel 2: MLP head + BCE. 8 rows per 256-thread block, k-split halves.
// ---------------------------------------------------------------------------
__global__ __launch_bounds__(256) void mlp_bce_kernel(
    const float* __restrict__ y_true,
    const float* __restrict__ W_hid,   // [H,H] row-major
    const float* __restrict__ b_hid,
    const float* __restrict__ W_out,
    const float* __restrict__ b_out,
    float*       __restrict__ out,
    int B)
{
    const int t    = threadIdx.x;
    const int row0 = blockIdx.x * RPB;
    const int kh   = t >> 7;           // k-half
    const int col  = t & 127;

    __shared__ float s_t[H][RPB];      // transposed sentence tile
    __shared__ float s_p[2][RPB][H];   // per-half partials
    __shared__ float red[RPB][4];

    for (int e = t; e < RPB * H; e += 256) {
        const int r = e >> 7;
        const int k = e & 127;
        const int row = min(row0 + r, B - 1);
        s_t[k][r] = g_sent[(size_t)row * H + k];
    }
    __syncthreads();

    float acc[RPB];
#pragma unroll
    for (int r = 0; r < RPB; r++) acc[r] = 0.f;

    const int k0 = kh * 64;
#pragma unroll 4
    for (int kk = 0; kk < 64; kk++) {
        const int k = k0 + kk;
        const float  wv = __ldg(&W_hid[k * H + col]);
        const float4 sa = *(const float4*)&s_t[k][0];
        const float4 sb = *(const float4*)&s_t[k][4];
        acc[0] += sa.x * wv;  acc[1] += sa.y * wv;
        acc[2] += sa.z * wv;  acc[3] += sa.w * wv;
        acc[4] += sb.x * wv;  acc[5] += sb.y * wv;
        acc[6] += sb.z * wv;  acc[7] += sb.w * wv;
    }
#pragma unroll
    for (int r = 0; r < RPB; r++) s_p[kh][r][col] = acc[r];
    __syncthreads();

    if (t < 128) {
        const float bh = b_hid[col];
        const float wo = W_out[col];
        float val[RPB];
#pragma unroll
        for (int r = 0; r < RPB; r++)
            val[r] = tanhf(s_p[0][r][col] + s_p[1][r][col] + bh) * wo;

#pragma unroll
        for (int off = 16; off > 0; off >>= 1)
#pragma unroll
            for (int r = 0; r < RPB; r++)
                val[r] += __shfl_xor_sync(0xffffffffu, val[r], off);

        if ((t & 31) == 0)
#pragma unroll
            for (int r = 0; r < RPB; r++) red[r][t >> 5] = val[r];
    }
    __syncthreads();

    if (t < RPB) {
        const int row = row0 + t;
        float loss = 0.f;
        if (row < B) {
            const float z = (red[t][0] + red[t][1]) +
                            (red[t][2] + red[t][3]) + __ldg(b_out);
            const float lp  = fmaxf(-log1pf(expf(-z)), -100.0f);
            const float l1m = fmaxf(-log1pf(expf(z)),  -100.0f);
            const float y   = __ldg(&y_true[row]);
            loss = -(y * lp + (1.0f - y) * l1m);
        }
#pragma unroll
        for (int off = 4; off > 0; off >>= 1)
            loss += __shfl_xor_sync(0x000000ffu, loss, off);
        if (t == 0) atomicAdd(out, loss);
    }
}

// ---------------------------------------------------------------------------
extern "C" void kernel_launch(void* const* d_in, const int* in_sizes, int n_in,
                              void* d_out, int out_size)
{
    const int*   token_ids = (const int*)d_in[0];
    const int*   seg_ids   = (const int*)d_in[1];
    const float* y_true    = (const float*)d_in[2];
    const float* embed     = (const float*)d_in[3];
    const float* W_hid     = (const float*)d_in[4];
    const float* b_hid     = (const float*)d_in[5];
    const float* W_out     = (const float*)d_in[6];
    const float* b_out     = (const float*)d_in[7];

    const int T = in_sizes[0];
    const int B = in_sizes[2];
    float* out = (float*)d_out;

    const int vthreads = (T + 7) / 8;
    prepass_kernel<<<(vthreads + 255) / 256, 256>>>(seg_ids, out, T, B);

    seg_mean_kernel<<<B, 128>>>(token_ids, embed);

    mlp_bce_kernel<<<(B + RPB - 1) / RPB, 256>>>(y_true, W_hid, b_hid,
                                                 W_out, b_out, out, B);
}